// round 14
// baseline (speedup 1.0000x reference)
#include <cuda_runtime.h>
#include <math.h>
#include <stdint.h>

#define NUM_CLASSES 10
#define BLOCK 256
#define GRID_MAIN 592
#define GRID_HIST 148
#define TILE_ROWS 512
#define TILE_F4 (TILE_ROWS * NUM_CLASSES / 4)   // 1280 float4 per tile

// log(x) = logf(x * 2^-21) + 21*ln2  (shift folded into final math)
#define LOG_SCALE (4.76837158203125e-7f)   // 2^-21
#define LOG_SHIFT 21.0

__device__ float  g_hist_partial[GRID_HIST * NUM_CLASSES];
__device__ float  g_counts[NUM_CLASSES];
__device__ double g_partial_log[GRID_MAIN];
__device__ double g_partial_sq[GRID_MAIN];
__device__ unsigned int g_hist_done = 0;   // reset by hist's last block each run
__device__ unsigned int g_done = 0;        // reset by main's last block each run

// ---------------------------------------------------------------------------
// Histogram of target (int32 in [0,10)) -> per-block partials -> ticket ->
// last block reduces (parallel) into g_counts.
// Triggers programmatic launch completion immediately so the dependent main
// kernel can start its prologue concurrently.
// ---------------------------------------------------------------------------
__global__ void __launch_bounds__(BLOCK)
cse_hist_kernel(const int* __restrict__ tgt, int n) {
    cudaTriggerProgrammaticLaunchCompletion();   // let main launch now

    __shared__ unsigned int s_hist[NUM_CLASSES];
    __shared__ float s_red[NUM_CLASSES];
    __shared__ bool s_last;
    const int tid = threadIdx.x;
    const int bid = blockIdx.x;
    if (tid < NUM_CLASSES) { s_hist[tid] = 0u; s_red[tid] = 0.0f; }
    __syncthreads();

    unsigned int c[NUM_CLASSES];
#pragma unroll
    for (int j = 0; j < NUM_CLASSES; j++) c[j] = 0u;

    const int4* t4 = reinterpret_cast<const int4*>(tgt);
    const int n4 = n >> 2;
    const int stride = GRID_HIST * BLOCK;

    // two independent packed-u64 streams -> 2x MLP on this latency-bound loop
    unsigned long long accA = 0ull, accB = 0ull;
    int since = 0;
    int i = bid * BLOCK + tid;
    for (; i + stride < n4; i += 2 * stride) {
        int4 va = t4[i];
        int4 vb = t4[i + stride];
        accA += (1ull << (6 * va.x)) + (1ull << (6 * va.y)) +
                (1ull << (6 * va.z)) + (1ull << (6 * va.w));
        accB += (1ull << (6 * vb.x)) + (1ull << (6 * vb.y)) +
                (1ull << (6 * vb.z)) + (1ull << (6 * vb.w));
        if (++since == 10) {              // <=40 increments per 6-bit field
#pragma unroll
            for (int j = 0; j < NUM_CLASSES; j++) {
                c[j] += (unsigned int)((accA >> (6 * j)) & 63ull);
                c[j] += (unsigned int)((accB >> (6 * j)) & 63ull);
            }
            accA = 0ull; accB = 0ull; since = 0;
        }
    }
    if (i < n4) {
        int4 va = t4[i];
        accA += (1ull << (6 * va.x)) + (1ull << (6 * va.y)) +
                (1ull << (6 * va.z)) + (1ull << (6 * va.w));
    }
#pragma unroll
    for (int j = 0; j < NUM_CLASSES; j++) {
        c[j] += (unsigned int)((accA >> (6 * j)) & 63ull);
        c[j] += (unsigned int)((accB >> (6 * j)) & 63ull);
    }
    if (bid == 0 && tid == 0) {           // tail rows (n % 4)
        for (int r = n4 * 4; r < n; r++) c[tgt[r]]++;
    }
#pragma unroll
    for (int j = 0; j < NUM_CLASSES; j++)
        if (c[j]) atomicAdd(&s_hist[j], c[j]);
    __syncthreads();
    if (tid < NUM_CLASSES)
        g_hist_partial[bid * NUM_CLASSES + tid] = (float)s_hist[tid];
    __threadfence();
    if (tid == 0) {
        unsigned int tkt = atomicAdd(&g_hist_done, 1u);
        s_last = (tkt == (unsigned int)(GRID_HIST - 1));
    }
    __syncthreads();
    if (s_last) {
        __threadfence();
        // parallel reduce of GRID_HIST*10 partials across all 256 threads
        for (int idx = tid; idx < GRID_HIST * NUM_CLASSES; idx += BLOCK)
            atomicAdd(&s_red[idx % NUM_CLASSES], g_hist_partial[idx]);
        __syncthreads();
        if (tid < NUM_CLASSES) g_counts[tid] = s_red[tid];
        if (tid == 0) g_hist_done = 0;    // reset for next graph replay
    }
}

// ---------------------------------------------------------------------------
// Main kernel: R13's measured-best phase B (plain cached loads, block-staged
// tiles) + PDL prologue (stage tile-0 before depending on hist's counts) +
// inline ticket finalize.
// ---------------------------------------------------------------------------
__global__ void __launch_bounds__(BLOCK, 1)
cse_main_kernel(const float* __restrict__ outp, int n_rows, float* __restrict__ out) {
    __shared__ __align__(16) float s_tile[TILE_ROWS * NUM_CLASSES]; // 20480 B
    __shared__ float s_cnt[NUM_CLASSES];
    __shared__ double s_rl[BLOCK / 32];
    __shared__ double s_rq[BLOCK / 32];
    __shared__ bool s_last;

    const int tid = threadIdx.x;
    const int bid = blockIdx.x;
    const int n_tiles = n_rows / TILE_ROWS;
    const float4* __restrict__ in4 = reinterpret_cast<const float4*>(outp);
    float4* s4 = reinterpret_cast<float4*>(s_tile);

    // ---- prologue: stage tile `bid` (independent of counts) ----------------
    if (bid < n_tiles) {
        size_t base4 = (size_t)bid * TILE_F4;
#pragma unroll
        for (int k = 0; k < 5; k++)
            s4[tid + k * BLOCK] = in4[base4 + tid + k * BLOCK];
    }

    // ---- wait for hist kernel's writes (counts), then read them ------------
    cudaGridDependencySynchronize();
    if (tid < NUM_CLASSES) s_cnt[tid] = g_counts[tid];
    __syncthreads();

    float c[NUM_CLASSES];
#pragma unroll
    for (int j = 0; j < NUM_CLASSES; j++) c[j] = s_cnt[j];

    double acc_log = 0.0;
    double acc_sq  = 0.0;
    float  prod    = 1.0f;
    int    pcnt    = 0;

    for (int tile = bid; tile < n_tiles; tile += GRID_MAIN) {
        // staged data (from prologue or previous iteration's stage) is visible
        // thanks to the __syncthreads() above / at loop bottom.

        // this thread's 2 rows: 20 floats, 16B-aligned (80B per thread)
        const float4* my = reinterpret_cast<const float4*>(s_tile + tid * 2 * NUM_CLASSES);
        float v[20];
#pragma unroll
        for (int k = 0; k < 5; k++) {
            float4 t = my[k];
            v[4 * k + 0] = t.x; v[4 * k + 1] = t.y;
            v[4 * k + 2] = t.z; v[4 * k + 3] = t.w;
        }

        float dot0 = 0.f, dot1 = 0.f, sq = 0.f;
#pragma unroll
        for (int j = 0; j < NUM_CLASSES; j++) {
            dot0 = fmaf(v[j], c[j], dot0);
            dot1 = fmaf(v[NUM_CLASSES + j], c[j], dot1);
        }
#pragma unroll
        for (int k = 0; k < 20; k++) sq = fmaf(v[k], v[k], sq);
        acc_sq += (double)sq;

        prod *= dot0 * LOG_SCALE;
        if (++pcnt == 8) { acc_log += (double)logf(prod); prod = 1.0f; pcnt = 0; }
        prod *= dot1 * LOG_SCALE;
        if (++pcnt == 8) { acc_log += (double)logf(prod); prod = 1.0f; pcnt = 0; }

        __syncthreads();                  // everyone done reading s_tile

        const int tn = tile + GRID_MAIN;  // stage next tile
        if (tn < n_tiles) {
            size_t base4 = (size_t)tn * TILE_F4;
#pragma unroll
            for (int k = 0; k < 5; k++)
                s4[tid + k * BLOCK] = in4[base4 + tid + k * BLOCK];
        }
        __syncthreads();                  // staged data visible for next iter
    }

    // tail rows (n_rows % TILE_ROWS), handled by block 0 directly from gmem
    const int tail_start = n_tiles * TILE_ROWS;
    if (bid == 0) {
        for (int r = tail_start + tid; r < n_rows; r += BLOCK) {
            const float* row = outp + (size_t)r * NUM_CLASSES;
            float dot = 0.f, sq = 0.f;
#pragma unroll
            for (int j = 0; j < NUM_CLASSES; j++) {
                float x = row[j];
                dot = fmaf(x, c[j], dot);
                sq  = fmaf(x, x, sq);
            }
            acc_sq  += (double)sq;
            acc_log += (double)logf(dot * LOG_SCALE);
        }
    }

    if (pcnt) acc_log += (double)logf(prod);

    // block reduction (deterministic order)
#pragma unroll
    for (int off = 16; off; off >>= 1) {
        acc_log += __shfl_down_sync(0xffffffffu, acc_log, off);
        acc_sq  += __shfl_down_sync(0xffffffffu, acc_sq,  off);
    }
    const int wid = tid >> 5, lane = tid & 31;
    if (lane == 0) { s_rl[wid] = acc_log; s_rq[wid] = acc_sq; }
    __syncthreads();
    if (tid == 0) {
        double a = 0.0, b = 0.0;
#pragma unroll
        for (int w = 0; w < BLOCK / 32; w++) { a += s_rl[w]; b += s_rq[w]; }
        g_partial_log[bid] = a;
        g_partial_sq[bid]  = b;
        __threadfence();
        unsigned int tkt = atomicAdd(&g_done, 1u);
        s_last = (tkt == (unsigned int)(GRID_MAIN - 1));
    }
    __syncthreads();

    // last-to-finish block: final reduction + scalar (no extra kernel launch)
    if (s_last) {
        __threadfence();
        double a = 0.0, b = 0.0;
        for (int i = tid; i < GRID_MAIN; i += BLOCK) {
            a += g_partial_log[i];
            b += g_partial_sq[i];
        }
#pragma unroll
        for (int off = 16; off; off >>= 1) {
            a += __shfl_down_sync(0xffffffffu, a, off);
            b += __shfl_down_sync(0xffffffffu, b, off);
        }
        if (lane == 0) { s_rl[wid] = a; s_rq[wid] = b; }
        __syncthreads();
        if (tid == 0) {
            double sa = 0.0, sb = 0.0;
#pragma unroll
            for (int w = 0; w < BLOCK / 32; w++) { sa += s_rl[w]; sb += s_rq[w]; }
            double N = (double)n_rows;
            double mean_log_nom = sa / N + LOG_SHIFT * M_LN2;
            double log_denom = 0.5 * log(sb) + 0.5 * log(N);   // log(||o||_F * sqrt(N))
            out[0] = (float)(log_denom - mean_log_nom);
            g_done = 0;        // reset for next graph replay
        }
    }
}

extern "C" void kernel_launch(void* const* d_in, const int* in_sizes, int n_in,
                              void* d_out, int out_size) {
    // Resolve inputs by size: outputs has NUM_CLASSES x the elements of target.
    int io = 0, it = 1;
    if (n_in >= 2 && in_sizes[1] > in_sizes[0]) { io = 1; it = 0; }
    const float* outputs = (const float*)d_in[io];
    const int*   tgt     = (const int*)d_in[it];      // int32
    const int    n_rows  = in_sizes[it];              // N samples
    float* out           = (float*)d_out;

    cse_hist_kernel<<<GRID_HIST, BLOCK>>>(tgt, n_rows);

    // Launch main with Programmatic Dependent Launch so its prologue (launch
    // ramp + tile-0 staging) overlaps the hist kernel. Fallback: plain launch
    // (cudaGridDependencySynchronize is then a no-op — dependencies already met).
    cudaLaunchConfig_t cfg = {};
    cfg.gridDim  = {GRID_MAIN, 1, 1};
    cfg.blockDim = {BLOCK, 1, 1};
    cfg.dynamicSmemBytes = 0;
    cudaLaunchAttribute attr[1];
    attr[0].id = cudaLaunchAttributeProgrammaticStreamSerialization;
    attr[0].val.programmaticStreamSerializationAllowed = 1;
    cfg.attrs = attr;
    cfg.numAttrs = 1;

    cudaError_t err = cudaLaunchKernelEx(&cfg, cse_main_kernel,
                                         outputs, n_rows, out);
    if (err != cudaSuccess) {
        (void)cudaGetLastError();         // clear; fall back to plain launch
        cse_main_kernel<<<GRID_MAIN, BLOCK>>>(outputs, n_rows, out);
    }
}